// round 4
// baseline (speedup 1.0000x reference)
#include <cuda_runtime.h>

#define NN 3000
#define TT 20
#define IND 6
#define HD 64
#define NH 8
#define MAXNZ 512

// ---------------- scratch (no allocation allowed) ----------------
__device__ float2 g_Whh2[HD * 192];         // recurrent weights, duplicated pairs [k][r]
__device__ float g_support[NN * HD];        // GRU final hidden
__device__ float g_s[2][NN * HD];           // per-graph head features  [n][h*8+f]
__device__ float g_f1[2][NH * NN];          // source scores  [g][h*N+n]
__device__ float g_f2[2][NH * NN];          // dest scores    [g][h*N+n]
__device__ unsigned g_f1maxI[16];           // encoded global per-(g,h) max of f1
__device__ float g_att[2][NN * HD];         // attention outputs
__device__ float g_emb[NN * HD];            // pre-pairnorm embedding
__device__ float g_colsum[HD];              // column sums for pairnorm mean

__device__ __forceinline__ float sigm(float x) { return 1.0f / (1.0f + __expf(-x)); }
__device__ __forceinline__ float tanhfast(float x) { return 2.0f * sigm(2.0f * x) - 1.0f; }

// order-preserving float<->uint encoding for atomicMax
__device__ __forceinline__ unsigned fenc(float f) {
    unsigned u = __float_as_uint(f);
    return (u & 0x80000000u) ? ~u : (u | 0x80000000u);
}
__device__ __forceinline__ float fdec(unsigned u) {
    return __uint_as_float((u & 0x80000000u) ? (u & 0x7fffffffu) : ~u);
}

// packed f32x2 helpers
__device__ __forceinline__ unsigned long long pk(float lo, float hi) {
    unsigned long long r;
    asm("mov.b64 %0, {%1,%2};" : "=l"(r) : "f"(lo), "f"(hi));
    return r;
}
__device__ __forceinline__ void upk(unsigned long long v, float& lo, float& hi) {
    asm("mov.b64 {%0,%1}, %2;" : "=f"(lo), "=f"(hi) : "l"(v));
}
__device__ __forceinline__ void ffma2(unsigned long long& d, unsigned long long a, unsigned long long b) {
    asm("fma.rn.f32x2 %0, %1, %2, %0;" : "+l"(d) : "l"(a), "l"(b));
}

// ---------------- K0: duplicate Whh pairs + init reductions ----------------
__global__ void prep_kernel(const float* __restrict__ Whh) {
    int i = blockIdx.x * 256 + threadIdx.x;
    if (i < 192 * HD) {
        int r = i >> 6, k = i & 63;
        float w = Whh[i];
        g_Whh2[k * 192 + r] = make_float2(w, w);
    }
    if (blockIdx.x == 0 && threadIdx.x < HD) g_colsum[threadIdx.x] = 0.f;
    if (blockIdx.x == 0 && threadIdx.x < 16) g_f1maxI[threadIdx.x] = 0u;
}

// ---------------- K1: GRU (8 nodes / 64-thread block) + fused head projection ----------------
__global__ void __launch_bounds__(64) gru_kernel(
        const float* __restrict__ x, const float* __restrict__ Wih,
        const float* __restrict__ bih, const float* __restrict__ bhh,
        const float* __restrict__ Wp, const float* __restrict__ Wn,
        const float* __restrict__ Wup, const float* __restrict__ Wvp,
        const float* __restrict__ Wun, const float* __restrict__ Wvn) {
    __shared__ float4 shh4[2][HD];   // [group][k] -> 4 nodes hidden each
    __shared__ float shx[IND][8];    // [c][b]
    int j = threadIdx.x;             // gate/hidden index 0..63
    int node0 = blockIdx.x * 8;      // 3000 / 8 = 375 blocks

    unsigned long long pwr[IND], pwz[IND], pwn[IND];
#pragma unroll
    for (int c = 0; c < IND; c++) {
        float a = Wih[j * IND + c];
        float b = Wih[(64 + j) * IND + c];
        float d = Wih[(128 + j) * IND + c];
        pwr[c] = pk(a, a); pwz[c] = pk(b, b); pwn[c] = pk(d, d);
    }
    float br  = bih[j] + bhh[j];
    float bz  = bih[64 + j] + bhh[64 + j];
    float bin = bih[128 + j];
    float bhn = bhh[128 + j];
    unsigned long long pbr = pk(br, br), pbz = pk(bz, bz);
    unsigned long long pbi = pk(bin, bin), pbh = pk(bhn, bhn);

    shh4[0][j] = make_float4(0.f, 0.f, 0.f, 0.f);
    shh4[1][j] = make_float4(0.f, 0.f, 0.f, 0.f);
    float h[8];
#pragma unroll
    for (int b = 0; b < 8; b++) h[b] = 0.f;

    const unsigned long long* w2 = (const unsigned long long*)g_Whh2;

    for (int t = 0; t < TT; t++) {
        if (j < 48) {
            int c = j >> 3, b = j & 7;
            shx[c][b] = x[((node0 + b) * TT + t) * IND + c];
        }
        __syncthreads();   // shx ready; prev shh writes visible

        unsigned long long ar[4], az[4], an_[4], gn[4];
#pragma unroll
        for (int p = 0; p < 4; p++) { ar[p] = pbr; az[p] = pbz; an_[p] = pbi; gn[p] = pbh; }

#pragma unroll
        for (int c = 0; c < IND; c++) {
            const float4* xf = (const float4*)shx[c];
            float4 xa = xf[0], xb = xf[1];
            unsigned long long xp[4] = { pk(xa.x, xa.y), pk(xa.z, xa.w),
                                         pk(xb.x, xb.y), pk(xb.z, xb.w) };
#pragma unroll
            for (int p = 0; p < 4; p++) {
                ffma2(ar[p], pwr[c], xp[p]);
                ffma2(az[p], pwz[c], xp[p]);
                ffma2(an_[p], pwn[c], xp[p]);
            }
        }

#pragma unroll 4
        for (int k = 0; k < HD; k++) {
            float4 ha = shh4[0][k], hb = shh4[1][k];
            unsigned long long hp[4] = { pk(ha.x, ha.y), pk(ha.z, ha.w),
                                         pk(hb.x, hb.y), pk(hb.z, hb.w) };
            unsigned long long w0 = w2[k * 192 + j];
            unsigned long long w1 = w2[k * 192 + 64 + j];
            unsigned long long wn2 = w2[k * 192 + 128 + j];
#pragma unroll
            for (int p = 0; p < 4; p++) {
                ffma2(ar[p], w0, hp[p]);
                ffma2(az[p], w1, hp[p]);
                ffma2(gn[p], wn2, hp[p]);
            }
        }
        __syncthreads();   // all reads of shh done before overwrite

#pragma unroll
        for (int p = 0; p < 4; p++) {
            float a0, a1, z0, z1, n0, n1, g0, g1;
            upk(ar[p], a0, a1); upk(az[p], z0, z1);
            upk(an_[p], n0, n1); upk(gn[p], g0, g1);
            float r0 = sigm(a0), r1 = sigm(a1);
            float zz0 = sigm(z0), zz1 = sigm(z1);
            float nv0 = tanhfast(n0 + r0 * g0);
            float nv1 = tanhfast(n1 + r1 * g1);
            h[2 * p]     = (1.f - zz0) * nv0 + zz0 * h[2 * p];
            h[2 * p + 1] = (1.f - zz1) * nv1 + zz1 * h[2 * p + 1];
        }
        shh4[0][j] = make_float4(h[0], h[1], h[2], h[3]);
        shh4[1][j] = make_float4(h[4], h[5], h[6], h[7]);
        if (t == TT - 1) __syncthreads();   // h fully written before fused tail reads
    }

#pragma unroll
    for (int b = 0; b < 8; b++) g_support[(node0 + b) * HD + j] = h[b];

    // ------ fused head projection: s = h @ W, f1/f2, global f1 max ------
    int hh = j >> 3, f = j & 7;
    const float* hsm = (const float*)shh4;   // [(b>>2)*64 + k]*4 + (b&3)
#pragma unroll
    for (int g = 0; g < 2; g++) {
        const float* W  = g ? Wn  : Wp;
        float wu = (g ? Wun : Wup)[hh * 8 + f];
        float wv = (g ? Wvn : Wvp)[hh * 8 + f];
        for (int b = 0; b < 8; b++) {
            const float* hb = hsm + ((b >> 2) * HD) * 4 + (b & 3);
            float a0 = 0.f, a1 = 0.f;
#pragma unroll 8
            for (int k = 0; k < HD; k += 2) {
                a0 += hb[k * 4] * W[k * HD + j];
                a1 += hb[(k + 1) * 4] * W[(k + 1) * HD + j];
            }
            float acc = a0 + a1;
            int n = node0 + b;
            g_s[g][n * HD + j] = acc;
            float t1 = acc * wu, t2 = acc * wv;
#pragma unroll
            for (int o = 4; o; o >>= 1) {
                t1 += __shfl_xor_sync(0xffffffffu, t1, o);
                t2 += __shfl_xor_sync(0xffffffffu, t2, o);
            }
            if (f == 0) {
                g_f1[g][hh * NN + n] = t1;
                g_f2[g][hh * NN + n] = t2;
                atomicMax(&g_f1maxI[g * 8 + hh], fenc(t1));
            }
        }
    }
}

// ---------------- K3: sparse masked attention, single pass (grid: [N, 2]) ----------------
__global__ void attn_kernel(const float* __restrict__ adj0, const float* __restrict__ adj1) {
    int i = blockIdx.x, g = blockIdx.y;
    const float* row = (g ? adj1 : adj0) + (size_t)i * NN;
    __shared__ int cnt;
    __shared__ short idx[MAXNZ];
    int tid = threadIdx.x, lane = tid & 31;
    if (tid == 0) cnt = 0;

    // prefetch the whole row slice to registers (MLP=3) before compaction
    const float4* row4 = (const float4*)row;   // N=3000 divisible by 4
    float4 v[3];
#pragma unroll
    for (int it = 0; it < 3; it++) {
        int q = it * 256 + tid;
        v[it] = (q < NN / 4) ? row4[q] : make_float4(0.f, 0.f, 0.f, 0.f);
    }
    __syncthreads();

#pragma unroll
    for (int it = 0; it < 3; it++) {
        int q = it * 256 + tid;
#pragma unroll
        for (int c = 0; c < 4; c++) {
            float val = (c == 0) ? v[it].x : (c == 1) ? v[it].y : (c == 2) ? v[it].z : v[it].w;
            unsigned bal = __ballot_sync(0xffffffffu, val != 0.f);
            if (bal) {
                int leader = __ffs(bal) - 1;
                int base;
                if (lane == leader) base = atomicAdd(&cnt, __popc(bal));
                base = __shfl_sync(0xffffffffu, base, leader);
                if (val != 0.f) {
                    int p = base + __popc(bal & ((1u << lane) - 1u));
                    if (p < MAXNZ) idx[p] = (short)(4 * q + c);
                }
            }
        }
    }
    __syncthreads();
    int m = min(cnt, MAXNZ);

    int h = tid >> 5;                         // warp = head
    const float* f1h = g_f1[g] + h * NN;
    float f2v = g_f2[g][h * NN + i];
    // shift M >= max over row nonzeros (leaky monotone; softmax shift-invariant)
    float Mv = fdec(g_f1maxI[g * 8 + h]) + f2v;
    Mv = Mv >= 0.f ? Mv : 0.2f * Mv;
    const float* sb = g_s[g];

    float se = 0.f;
    float acc[8] = {0, 0, 0, 0, 0, 0, 0, 0};
    for (int k = lane; k < m; k += 32) {
        int j = idx[k];
        float vv = f1h[j] + f2v;
        vv = vv >= 0.f ? vv : 0.2f * vv;
        float e = __expf(vv - Mv);
        se += e;
        const float4* sp = (const float4*)(sb + j * HD + h * 8);
        float4 a = sp[0], bb = sp[1];
        acc[0] += e * a.x;  acc[1] += e * a.y;  acc[2] += e * a.z;  acc[3] += e * a.w;
        acc[4] += e * bb.x; acc[5] += e * bb.y; acc[6] += e * bb.z; acc[7] += e * bb.w;
    }
#pragma unroll
    for (int o = 16; o; o >>= 1) {
        se += __shfl_xor_sync(0xffffffffu, se, o);
#pragma unroll
        for (int f = 0; f < 8; f++) acc[f] += __shfl_xor_sync(0xffffffffu, acc[f], o);
    }
    if (lane == 0) {
        float inv = se > 0.f ? 1.0f / se : 0.f;   // empty row -> zeros (matches ref mask)
        float* o2 = g_att[g] + i * HD + h * 8;
#pragma unroll
        for (int f = 0; f < 8; f++) o2[f] = acc[f] * inv;
    }
}

// ---------------- K4: residual/proj + MLPs + semantic attention (grid: N/4) ----------------
__global__ void comb_kernel(const float* __restrict__ pos_b, const float* __restrict__ pWp, const float* __restrict__ pbp,
                            const float* __restrict__ neg_b, const float* __restrict__ pWn, const float* __restrict__ pbn,
                            const float* __restrict__ selfW, const float* __restrict__ selfb,
                            const float* __restrict__ mpW, const float* __restrict__ mpb,
                            const float* __restrict__ mnW, const float* __restrict__ mnb,
                            const float* __restrict__ semW1, const float* __restrict__ semb1,
                            const float* __restrict__ semW2) {
    int c = threadIdx.x;   // 64
    __shared__ float sup[HD], ps[HD], ns[HD], e0[HD], e1[HD], e2[HD];
    __shared__ float red[2][3];
    int n0 = blockIdx.x * 4;
    int warp = c >> 5, lane = c & 31;
    float colpart = 0.f;
    for (int b = 0; b < 4; b++) {
        int n = n0 + b;
        sup[c] = g_support[n * HD + c];
        __syncthreads();
        float ap0 = g_att[0][n * HD + c] + pos_b[c] + pbp[c], ap1 = 0.f;
        float an0 = g_att[1][n * HD + c] + neg_b[c] + pbn[c], an1 = 0.f;
        float sv0 = selfb[c], sv1 = 0.f;
#pragma unroll 4
        for (int k = 0; k < HD; k += 2) {
            float s0 = sup[k], s1 = sup[k + 1];
            ap0 += s0 * pWp[k * HD + c];      ap1 += s1 * pWp[(k + 1) * HD + c];
            an0 += s0 * pWn[k * HD + c];      an1 += s1 * pWn[(k + 1) * HD + c];
            sv0 += s0 * selfW[k * HD + c];    sv1 += s1 * selfW[(k + 1) * HD + c];
        }
        float ap = ap0 + ap1, an = an0 + an1, sv = sv0 + sv1;
        ps[c] = ap; ns[c] = an;
        __syncthreads();
        float sp0 = mpb[c], sp1 = 0.f, sn0 = mnb[c], sn1 = 0.f;
#pragma unroll 4
        for (int k = 0; k < HD; k += 2) {
            sp0 += ps[k] * mpW[k * HD + c];   sp1 += ps[k + 1] * mpW[(k + 1) * HD + c];
            sn0 += ns[k] * mnW[k * HD + c];   sn1 += ns[k + 1] * mnW[(k + 1) * HD + c];
        }
        float spv = sp0 + sp1, snv = sn0 + sn1;
        e0[c] = sv; e1[c] = spv; e2[c] = snv;
        __syncthreads();
        float t00 = semb1[c], t01 = 0.f, t10 = semb1[c], t11 = 0.f, t20 = semb1[c], t21 = 0.f;
#pragma unroll 4
        for (int k = 0; k < HD; k += 2) {
            float w0 = semW1[k * HD + c], w1 = semW1[(k + 1) * HD + c];
            t00 += e0[k] * w0; t01 += e0[k + 1] * w1;
            t10 += e1[k] * w0; t11 += e1[k + 1] * w1;
            t20 += e2[k] * w0; t21 += e2[k + 1] * w1;
        }
        float w2v = semW2[c];
        float t0 = tanhfast(t00 + t01) * w2v;
        float t1 = tanhfast(t10 + t11) * w2v;
        float t2 = tanhfast(t20 + t21) * w2v;
#pragma unroll
        for (int o = 16; o; o >>= 1) {
            t0 += __shfl_xor_sync(0xffffffffu, t0, o);
            t1 += __shfl_xor_sync(0xffffffffu, t1, o);
            t2 += __shfl_xor_sync(0xffffffffu, t2, o);
        }
        if (lane == 0) { red[warp][0] = t0; red[warp][1] = t1; red[warp][2] = t2; }
        __syncthreads();
        float w0  = red[0][0] + red[1][0];
        float w1  = red[0][1] + red[1][1];
        float ww2 = red[0][2] + red[1][2];
        float mw = fmaxf(w0, fmaxf(w1, ww2));
        float b0 = __expf(w0 - mw), b1 = __expf(w1 - mw), b2 = __expf(ww2 - mw);
        float inv = 1.f / (b0 + b1 + b2);
        float emb = (b0 * sv + b1 * spv + b2 * snv) * inv;
        g_emb[n * HD + c] = emb;
        colpart += emb;
    }
    atomicAdd(&g_colsum[c], colpart);
}

// ---------------- K5: pairnorm + prediction head (warp per node) ----------------
__global__ void final_kernel(const float* __restrict__ predW, const float* __restrict__ predb,
                             float* __restrict__ out) {
    int warp = threadIdx.x >> 5, lane = threadIdx.x & 31;
    int n = blockIdx.x * 4 + warp;
    float invn = 1.0f / NN;
    float x0 = g_emb[n * HD + lane]      - g_colsum[lane]      * invn;
    float x1 = g_emb[n * HD + 32 + lane] - g_colsum[32 + lane] * invn;
    float ss = x0 * x0 + x1 * x1;
    float dt = x0 * predW[lane] + x1 * predW[32 + lane];
#pragma unroll
    for (int o = 16; o; o >>= 1) {
        ss += __shfl_xor_sync(0xffffffffu, ss, o);
        dt += __shfl_xor_sync(0xffffffffu, dt, o);
    }
    if (lane == 0) out[n] = sigm(dt * rsqrtf(1e-6f + ss) + predb[0]);
}

// ---------------- launch ----------------
extern "C" void kernel_launch(void* const* d_in, const int* in_sizes, int n_in,
                              void* d_out, int out_size) {
    (void)in_sizes; (void)n_in; (void)out_size;
    const float* inputs   = (const float*)d_in[0];
    const float* pos_adj  = (const float*)d_in[1];
    const float* neg_adj  = (const float*)d_in[2];
    const float* Wih      = (const float*)d_in[3];
    const float* Whh      = (const float*)d_in[4];
    const float* bih      = (const float*)d_in[5];
    const float* bhh      = (const float*)d_in[6];
    const float* pos_W    = (const float*)d_in[7];
    const float* pos_Wu   = (const float*)d_in[8];
    const float* pos_Wv   = (const float*)d_in[9];
    const float* pos_b    = (const float*)d_in[10];
    const float* pos_projW= (const float*)d_in[11];
    const float* pos_projb= (const float*)d_in[12];
    const float* neg_W    = (const float*)d_in[13];
    const float* neg_Wu   = (const float*)d_in[14];
    const float* neg_Wv   = (const float*)d_in[15];
    const float* neg_b    = (const float*)d_in[16];
    const float* neg_projW= (const float*)d_in[17];
    const float* neg_projb= (const float*)d_in[18];
    const float* self_W   = (const float*)d_in[19];
    const float* self_b   = (const float*)d_in[20];
    const float* mlpp_W   = (const float*)d_in[21];
    const float* mlpp_b   = (const float*)d_in[22];
    const float* mlpn_W   = (const float*)d_in[23];
    const float* mlpn_b   = (const float*)d_in[24];
    const float* sem_W1   = (const float*)d_in[25];
    const float* sem_b1   = (const float*)d_in[26];
    const float* sem_W2   = (const float*)d_in[27];
    const float* pred_W   = (const float*)d_in[28];
    const float* pred_b   = (const float*)d_in[29];

    prep_kernel<<<48, 256>>>(Whh);
    gru_kernel<<<NN / 8, 64>>>(inputs, Wih, bih, bhh,
                               pos_W, neg_W, pos_Wu, pos_Wv, neg_Wu, neg_Wv);
    attn_kernel<<<dim3(NN, 2), 256>>>(pos_adj, neg_adj);
    comb_kernel<<<NN / 4, 64>>>(pos_b, pos_projW, pos_projb, neg_b, neg_projW, neg_projb,
                                self_W, self_b, mlpp_W, mlpp_b, mlpn_W, mlpn_b,
                                sem_W1, sem_b1, sem_W2);
    final_kernel<<<NN / 4, 128>>>(pred_W, pred_b, (float*)d_out);
}

// round 5
// speedup vs baseline: 1.2429x; 1.2429x over previous
#include <cuda_runtime.h>

#define NN 3000
#define TT 20
#define IND 6
#define HD 64
#define NH 8
#define MAXNZ 512

// ---------------- scratch (no allocation allowed) ----------------
__device__ float2 g_Whh2[HD * 192];         // recurrent weights, duplicated pairs [k][r]
__device__ float g_support[NN * HD];        // GRU final hidden
__device__ float g_s[2][NN * HD];           // per-graph head features  [n][h*8+f]
__device__ float g_f1[2][NH * NN];          // source scores  [g][h*N+n]
__device__ float g_f2[2][NH * NN];          // dest scores    [g][h*N+n]
__device__ unsigned g_f1maxI[16];           // encoded global per-(g,h) max of f1
__device__ float g_att[2][NN * HD];         // attention outputs
__device__ float g_emb[NN * HD];            // pre-pairnorm embedding
__device__ float g_colsum[HD];              // column sums for pairnorm mean

__device__ __forceinline__ float sigm(float x) { return 1.0f / (1.0f + __expf(-x)); }
__device__ __forceinline__ float tanhfast(float x) { return 2.0f * sigm(2.0f * x) - 1.0f; }

// order-preserving float<->uint encoding for atomicMax
__device__ __forceinline__ unsigned fenc(float f) {
    unsigned u = __float_as_uint(f);
    return (u & 0x80000000u) ? ~u : (u | 0x80000000u);
}
__device__ __forceinline__ float fdec(unsigned u) {
    return __uint_as_float((u & 0x80000000u) ? (u & 0x7fffffffu) : ~u);
}

// packed f32x2 helpers
__device__ __forceinline__ unsigned long long pk(float lo, float hi) {
    unsigned long long r;
    asm("mov.b64 %0, {%1,%2};" : "=l"(r) : "f"(lo), "f"(hi));
    return r;
}
__device__ __forceinline__ void upk(unsigned long long v, float& lo, float& hi) {
    asm("mov.b64 {%0,%1}, %2;" : "=f"(lo), "=f"(hi) : "l"(v));
}
__device__ __forceinline__ void ffma2(unsigned long long& d, unsigned long long a, unsigned long long b) {
    asm("fma.rn.f32x2 %0, %1, %2, %0;" : "+l"(d) : "l"(a), "l"(b));
}

// ---------------- K0: duplicate Whh pairs + init reductions ----------------
__global__ void prep_kernel(const float* __restrict__ Whh) {
    int i = blockIdx.x * 256 + threadIdx.x;
    if (i < 192 * HD) {
        int r = i >> 6, k = i & 63;
        float w = Whh[i];
        g_Whh2[k * 192 + r] = make_float2(w, w);
    }
    if (blockIdx.x == 0 && threadIdx.x < HD) g_colsum[threadIdx.x] = 0.f;
    if (blockIdx.x == 0 && threadIdx.x < 16) g_f1maxI[threadIdx.x] = 0u;
}

// ---------------- K1: GRU (4 nodes / 64-thread block) + fused head projection ----------------
__global__ void __launch_bounds__(64) gru_kernel(
        const float* __restrict__ x, const float* __restrict__ Wih,
        const float* __restrict__ bih, const float* __restrict__ bhh,
        const float* __restrict__ Wp, const float* __restrict__ Wn,
        const float* __restrict__ Wup, const float* __restrict__ Wvp,
        const float* __restrict__ Wun, const float* __restrict__ Wvn) {
    __shared__ float4 shh4[HD];    // [k] -> 4 nodes hidden
    __shared__ float4 shx4[IND];   // [c] -> 4 nodes input
    float* shxf = (float*)shx4;
    int j = threadIdx.x;           // gate/hidden index 0..63
    int node0 = blockIdx.x * 4;    // 750 blocks

    unsigned long long pwr[IND], pwz[IND], pwn[IND];
#pragma unroll
    for (int c = 0; c < IND; c++) {
        float a = Wih[j * IND + c];
        float b = Wih[(64 + j) * IND + c];
        float d = Wih[(128 + j) * IND + c];
        pwr[c] = pk(a, a); pwz[c] = pk(b, b); pwn[c] = pk(d, d);
    }
    float br  = bih[j] + bhh[j];
    float bz  = bih[64 + j] + bhh[64 + j];
    float bin = bih[128 + j];
    float bhn = bhh[128 + j];
    unsigned long long pbr = pk(br, br), pbz = pk(bz, bz);
    unsigned long long pbi = pk(bin, bin), pbh = pk(bhn, bhn);

    shh4[j] = make_float4(0.f, 0.f, 0.f, 0.f);
    float h0 = 0.f, h1 = 0.f, h2 = 0.f, h3 = 0.f;

    const unsigned long long* w2 = (const unsigned long long*)g_Whh2;

    for (int t = 0; t < TT; t++) {
        if (j < 24) {
            int c = j >> 2, b = j & 3;
            shxf[c * 4 + b] = x[((node0 + b) * TT + t) * IND + c];
        }
        __syncthreads();   // shx ready; prev shh writes visible

        unsigned long long ar01 = pbr, ar23 = pbr;
        unsigned long long az01 = pbz, az23 = pbz;
        unsigned long long an01 = pbi, an23 = pbi;
        unsigned long long gn01 = pbh, gn23 = pbh;

#pragma unroll
        for (int c = 0; c < IND; c++) {
            float4 xv = shx4[c];
            unsigned long long x01 = pk(xv.x, xv.y), x23 = pk(xv.z, xv.w);
            ffma2(ar01, pwr[c], x01); ffma2(ar23, pwr[c], x23);
            ffma2(az01, pwz[c], x01); ffma2(az23, pwz[c], x23);
            ffma2(an01, pwn[c], x01); ffma2(an23, pwn[c], x23);
        }

#pragma unroll 4
        for (int k = 0; k < HD; k++) {
            float4 hv = shh4[k];
            unsigned long long h01 = pk(hv.x, hv.y), h23 = pk(hv.z, hv.w);
            unsigned long long w0 = w2[k * 192 + j];
            unsigned long long w1 = w2[k * 192 + 64 + j];
            unsigned long long wn2 = w2[k * 192 + 128 + j];
            ffma2(ar01, w0, h01);  ffma2(ar23, w0, h23);
            ffma2(az01, w1, h01);  ffma2(az23, w1, h23);
            ffma2(gn01, wn2, h01); ffma2(gn23, wn2, h23);
        }
        __syncthreads();   // all reads of shh done before overwrite

        float a0, a1, a2, a3, z0, z1, z2, z3, n0, n1, n2, n3, g0, g1, g2, g3;
        upk(ar01, a0, a1); upk(ar23, a2, a3);
        upk(az01, z0, z1); upk(az23, z2, z3);
        upk(an01, n0, n1); upk(an23, n2, n3);
        upk(gn01, g0, g1); upk(gn23, g2, g3);

        float r0 = sigm(a0), r1 = sigm(a1), r2 = sigm(a2), r3 = sigm(a3);
        float zz0 = sigm(z0), zz1 = sigm(z1), zz2 = sigm(z2), zz3 = sigm(z3);
        float nv0 = tanhfast(n0 + r0 * g0);
        float nv1 = tanhfast(n1 + r1 * g1);
        float nv2 = tanhfast(n2 + r2 * g2);
        float nv3 = tanhfast(n3 + r3 * g3);
        h0 = (1.f - zz0) * nv0 + zz0 * h0;
        h1 = (1.f - zz1) * nv1 + zz1 * h1;
        h2 = (1.f - zz2) * nv2 + zz2 * h2;
        h3 = (1.f - zz3) * nv3 + zz3 * h3;
        shh4[j] = make_float4(h0, h1, h2, h3);
    }
    __syncthreads();   // h fully written before fused tail reads

    g_support[(node0 + 0) * HD + j] = h0;
    g_support[(node0 + 1) * HD + j] = h1;
    g_support[(node0 + 2) * HD + j] = h2;
    g_support[(node0 + 3) * HD + j] = h3;

    // ------ fused head projection: s = h @ W, f1/f2, global f1 max ------
    int hh = j >> 3, f = j & 7;
    const float* hsm = (const float*)shh4;   // [k*4 + b]
#pragma unroll
    for (int g = 0; g < 2; g++) {
        const float* W  = g ? Wn  : Wp;
        float wu = (g ? Wun : Wup)[hh * 8 + f];
        float wv = (g ? Wvn : Wvp)[hh * 8 + f];
        float acc[4] = {0.f, 0.f, 0.f, 0.f};
#pragma unroll 4
        for (int k = 0; k < HD; k++) {
            float w = W[k * HD + j];
#pragma unroll
            for (int b = 0; b < 4; b++) acc[b] += hsm[k * 4 + b] * w;
        }
#pragma unroll
        for (int b = 0; b < 4; b++) {
            int n = node0 + b;
            g_s[g][n * HD + j] = acc[b];
            float t1 = acc[b] * wu, t2 = acc[b] * wv;
#pragma unroll
            for (int o = 4; o; o >>= 1) {
                t1 += __shfl_xor_sync(0xffffffffu, t1, o);
                t2 += __shfl_xor_sync(0xffffffffu, t2, o);
            }
            if (f == 0) {
                g_f1[g][hh * NN + n] = t1;
                g_f2[g][hh * NN + n] = t2;
                atomicMax(&g_f1maxI[g * 8 + hh], fenc(t1));
            }
        }
    }
}

// ---------------- K3: sparse masked attention, single pass (grid: [N, 2]) ----------------
__global__ void attn_kernel(const float* __restrict__ adj0, const float* __restrict__ adj1) {
    int i = blockIdx.x, g = blockIdx.y;
    const float* row = (g ? adj1 : adj0) + (size_t)i * NN;
    __shared__ int cnt;
    __shared__ short idx[MAXNZ];
    int tid = threadIdx.x, lane = tid & 31;
    if (tid == 0) cnt = 0;

    // prefetch the whole row slice to registers (MLP=3) before compaction
    const float4* row4 = (const float4*)row;   // N=3000 divisible by 4
    float4 v[3];
#pragma unroll
    for (int it = 0; it < 3; it++) {
        int q = it * 256 + tid;
        v[it] = (q < NN / 4) ? row4[q] : make_float4(0.f, 0.f, 0.f, 0.f);
    }
    __syncthreads();

#pragma unroll
    for (int it = 0; it < 3; it++) {
        int q = it * 256 + tid;
#pragma unroll
        for (int c = 0; c < 4; c++) {
            float val = (c == 0) ? v[it].x : (c == 1) ? v[it].y : (c == 2) ? v[it].z : v[it].w;
            unsigned bal = __ballot_sync(0xffffffffu, val != 0.f);
            if (bal) {
                int leader = __ffs(bal) - 1;
                int base;
                if (lane == leader) base = atomicAdd(&cnt, __popc(bal));
                base = __shfl_sync(0xffffffffu, base, leader);
                if (val != 0.f) {
                    int p = base + __popc(bal & ((1u << lane) - 1u));
                    if (p < MAXNZ) idx[p] = (short)(4 * q + c);
                }
            }
        }
    }
    __syncthreads();
    int m = min(cnt, MAXNZ);

    int h = tid >> 5;                         // warp = head
    const float* f1h = g_f1[g] + h * NN;
    float f2v = g_f2[g][h * NN + i];
    // shift M >= max over row nonzeros (leaky monotone; softmax shift-invariant)
    float Mv = fdec(g_f1maxI[g * 8 + h]) + f2v;
    Mv = Mv >= 0.f ? Mv : 0.2f * Mv;
    const float* sb = g_s[g];

    float se = 0.f;
    float acc[8] = {0, 0, 0, 0, 0, 0, 0, 0};
    for (int k = lane; k < m; k += 32) {
        int j = idx[k];
        float vv = f1h[j] + f2v;
        vv = vv >= 0.f ? vv : 0.2f * vv;
        float e = __expf(vv - Mv);
        se += e;
        const float4* sp = (const float4*)(sb + j * HD + h * 8);
        float4 a = sp[0], bb = sp[1];
        acc[0] += e * a.x;  acc[1] += e * a.y;  acc[2] += e * a.z;  acc[3] += e * a.w;
        acc[4] += e * bb.x; acc[5] += e * bb.y; acc[6] += e * bb.z; acc[7] += e * bb.w;
    }
#pragma unroll
    for (int o = 16; o; o >>= 1) {
        se += __shfl_xor_sync(0xffffffffu, se, o);
#pragma unroll
        for (int f = 0; f < 8; f++) acc[f] += __shfl_xor_sync(0xffffffffu, acc[f], o);
    }
    if (lane == 0) {
        float inv = se > 0.f ? 1.0f / se : 0.f;   // empty row -> zeros (matches ref mask)
        float* o2 = g_att[g] + i * HD + h * 8;
#pragma unroll
        for (int f = 0; f < 8; f++) o2[f] = acc[f] * inv;
    }
}

// ---------------- K4: warp-per-2-nodes residual/proj + MLPs + semantic attention ----------------
// grid: ceil(N/16), block 256 (8 warps x 2 nodes)
__global__ void __launch_bounds__(256) comb_kernel(
        const float* __restrict__ pos_b, const float* __restrict__ pWp, const float* __restrict__ pbp,
        const float* __restrict__ neg_b, const float* __restrict__ pWn, const float* __restrict__ pbn,
        const float* __restrict__ selfW, const float* __restrict__ selfb,
        const float* __restrict__ mpW, const float* __restrict__ mpb,
        const float* __restrict__ mnW, const float* __restrict__ mnb,
        const float* __restrict__ semW1, const float* __restrict__ semb1,
        const float* __restrict__ semW2) {
    __shared__ float sb[8][12][HD];     // per-warp staging
    __shared__ float colacc[HD];
    int tid = threadIdx.x, warp = tid >> 5, lane = tid & 31;
    int nA = blockIdx.x * 16 + warp * 2;
    int c0 = lane, c1 = lane + 32;
    bool act = (nA < NN);

    if (tid < HD) colacc[tid] = 0.f;
    __syncthreads();

    if (act) {
        int nB = nA + 1;   // NN even, nA even -> nB valid
        float (*S)[HD] = sb[warp];
        // 0 supA  1 supB  2 psA  3 psB  4 nsA  5 nsB  6 e0A  7 e0B  8 e1A  9 e1B  10 e2A  11 e2B
        S[0][c0] = g_support[nA * HD + c0]; S[0][c1] = g_support[nA * HD + c1];
        S[1][c0] = g_support[nB * HD + c0]; S[1][c1] = g_support[nB * HD + c1];
        __syncwarp();

        // ---- phase 1: ap = att0 + b + proj, an = att1 + b + proj, sv = self ----
        float bp0 = pos_b[c0] + pbp[c0], bp1 = pos_b[c1] + pbp[c1];
        float bn0 = neg_b[c0] + pbn[c0], bn1 = neg_b[c1] + pbn[c1];
        float apA0 = g_att[0][nA * HD + c0] + bp0, apA1 = g_att[0][nA * HD + c1] + bp1;
        float apB0 = g_att[0][nB * HD + c0] + bp0, apB1 = g_att[0][nB * HD + c1] + bp1;
        float anA0 = g_att[1][nA * HD + c0] + bn0, anA1 = g_att[1][nA * HD + c1] + bn1;
        float anB0 = g_att[1][nB * HD + c0] + bn0, anB1 = g_att[1][nB * HD + c1] + bn1;
        float svA0 = selfb[c0], svA1 = selfb[c1];
        float svB0 = svA0, svB1 = svA1;
#pragma unroll 4
        for (int k = 0; k < HD; k++) {
            float sA = S[0][k], sBv = S[1][k];
            float wp0 = pWp[k * HD + c0], wp1 = pWp[k * HD + c1];
            float wn0 = pWn[k * HD + c0], wn1 = pWn[k * HD + c1];
            float ws0 = selfW[k * HD + c0], ws1 = selfW[k * HD + c1];
            apA0 += sA * wp0;  apA1 += sA * wp1;  apB0 += sBv * wp0;  apB1 += sBv * wp1;
            anA0 += sA * wn0;  anA1 += sA * wn1;  anB0 += sBv * wn0;  anB1 += sBv * wn1;
            svA0 += sA * ws0;  svA1 += sA * ws1;  svB0 += sBv * ws0;  svB1 += sBv * ws1;
        }
        S[2][c0] = apA0; S[2][c1] = apA1; S[3][c0] = apB0; S[3][c1] = apB1;
        S[4][c0] = anA0; S[4][c1] = anA1; S[5][c0] = anB0; S[5][c1] = anB1;
        __syncwarp();

        // ---- phase 2: sp = ps @ mpW + mpb, sn = ns @ mnW + mnb ----
        float spA0 = mpb[c0], spA1 = mpb[c1], spB0 = spA0, spB1 = spA1;
        float snA0 = mnb[c0], snA1 = mnb[c1], snB0 = snA0, snB1 = snA1;
#pragma unroll 4
        for (int k = 0; k < HD; k++) {
            float pA = S[2][k], pB = S[3][k], qA = S[4][k], qB = S[5][k];
            float w0 = mpW[k * HD + c0], w1 = mpW[k * HD + c1];
            float v0 = mnW[k * HD + c0], v1 = mnW[k * HD + c1];
            spA0 += pA * w0; spA1 += pA * w1; spB0 += pB * w0; spB1 += pB * w1;
            snA0 += qA * v0; snA1 += qA * v1; snB0 += qB * v0; snB1 += qB * v1;
        }
        S[6][c0] = svA0; S[6][c1] = svA1; S[7][c0] = svB0; S[7][c1] = svB1;
        S[8][c0] = spA0; S[8][c1] = spA1; S[9][c0] = spB0; S[9][c1] = spB1;
        S[10][c0] = snA0; S[10][c1] = snA1; S[11][c0] = snB0; S[11][c1] = snB1;
        __syncwarp();

        // ---- phase 3: semantic attention logits ----
        float b10 = semb1[c0], b11 = semb1[c1];
        float tA00 = b10, tA01 = b11, tA10 = b10, tA11 = b11, tA20 = b10, tA21 = b11;
        float tB00 = b10, tB01 = b11, tB10 = b10, tB11 = b11, tB20 = b10, tB21 = b11;
#pragma unroll 4
        for (int k = 0; k < HD; k++) {
            float w0 = semW1[k * HD + c0], w1 = semW1[k * HD + c1];
            float e0A = S[6][k], e0B = S[7][k];
            float e1A = S[8][k], e1B = S[9][k];
            float e2A = S[10][k], e2B = S[11][k];
            tA00 += e0A * w0; tA01 += e0A * w1; tB00 += e0B * w0; tB01 += e0B * w1;
            tA10 += e1A * w0; tA11 += e1A * w1; tB10 += e1B * w0; tB11 += e1B * w1;
            tA20 += e2A * w0; tA21 += e2A * w1; tB20 += e2B * w0; tB21 += e2B * w1;
        }
        float w2v0 = semW2[c0], w2v1 = semW2[c1];
        float uA0 = tanhfast(tA00) * w2v0 + tanhfast(tA01) * w2v1;
        float uA1 = tanhfast(tA10) * w2v0 + tanhfast(tA11) * w2v1;
        float uA2 = tanhfast(tA20) * w2v0 + tanhfast(tA21) * w2v1;
        float uB0 = tanhfast(tB00) * w2v0 + tanhfast(tB01) * w2v1;
        float uB1 = tanhfast(tB10) * w2v0 + tanhfast(tB11) * w2v1;
        float uB2 = tanhfast(tB20) * w2v0 + tanhfast(tB21) * w2v1;
#pragma unroll
        for (int o = 16; o; o >>= 1) {
            uA0 += __shfl_xor_sync(0xffffffffu, uA0, o);
            uA1 += __shfl_xor_sync(0xffffffffu, uA1, o);
            uA2 += __shfl_xor_sync(0xffffffffu, uA2, o);
            uB0 += __shfl_xor_sync(0xffffffffu, uB0, o);
            uB1 += __shfl_xor_sync(0xffffffffu, uB1, o);
            uB2 += __shfl_xor_sync(0xffffffffu, uB2, o);
        }
        // 3-way softmax + combine (node A)
        float mA = fmaxf(uA0, fmaxf(uA1, uA2));
        float eA0 = __expf(uA0 - mA), eA1 = __expf(uA1 - mA), eA2 = __expf(uA2 - mA);
        float invA = 1.f / (eA0 + eA1 + eA2);
        float embA0 = (eA0 * svA0 + eA1 * spA0 + eA2 * snA0) * invA;
        float embA1 = (eA0 * svA1 + eA1 * spA1 + eA2 * snA1) * invA;
        // node B
        float mB = fmaxf(uB0, fmaxf(uB1, uB2));
        float eB0 = __expf(uB0 - mB), eB1 = __expf(uB1 - mB), eB2 = __expf(uB2 - mB);
        float invB = 1.f / (eB0 + eB1 + eB2);
        float embB0 = (eB0 * svB0 + eB1 * spB0 + eB2 * snB0) * invB;
        float embB1 = (eB0 * svB1 + eB1 * spB1 + eB2 * snB1) * invB;

        g_emb[nA * HD + c0] = embA0; g_emb[nA * HD + c1] = embA1;
        g_emb[nB * HD + c0] = embB0; g_emb[nB * HD + c1] = embB1;
        atomicAdd(&colacc[c0], embA0 + embB0);
        atomicAdd(&colacc[c1], embA1 + embB1);
    }
    __syncthreads();
    if (tid < HD) atomicAdd(&g_colsum[tid], colacc[tid]);
}

// ---------------- K5: pairnorm + prediction head (warp per node) ----------------
__global__ void final_kernel(const float* __restrict__ predW, const float* __restrict__ predb,
                             float* __restrict__ out) {
    int warp = threadIdx.x >> 5, lane = threadIdx.x & 31;
    int n = blockIdx.x * 4 + warp;
    float invn = 1.0f / NN;
    float x0 = g_emb[n * HD + lane]      - g_colsum[lane]      * invn;
    float x1 = g_emb[n * HD + 32 + lane] - g_colsum[32 + lane] * invn;
    float ss = x0 * x0 + x1 * x1;
    float dt = x0 * predW[lane] + x1 * predW[32 + lane];
#pragma unroll
    for (int o = 16; o; o >>= 1) {
        ss += __shfl_xor_sync(0xffffffffu, ss, o);
        dt += __shfl_xor_sync(0xffffffffu, dt, o);
    }
    if (lane == 0) out[n] = sigm(dt * rsqrtf(1e-6f + ss) + predb[0]);
}

// ---------------- launch ----------------
extern "C" void kernel_launch(void* const* d_in, const int* in_sizes, int n_in,
                              void* d_out, int out_size) {
    (void)in_sizes; (void)n_in; (void)out_size;
    const float* inputs   = (const float*)d_in[0];
    const float* pos_adj  = (const float*)d_in[1];
    const float* neg_adj  = (const float*)d_in[2];
    const float* Wih      = (const float*)d_in[3];
    const float* Whh      = (const float*)d_in[4];
    const float* bih      = (const float*)d_in[5];
    const float* bhh      = (const float*)d_in[6];
    const float* pos_W    = (const float*)d_in[7];
    const float* pos_Wu   = (const float*)d_in[8];
    const float* pos_Wv   = (const float*)d_in[9];
    const float* pos_b    = (const float*)d_in[10];
    const float* pos_projW= (const float*)d_in[11];
    const float* pos_projb= (const float*)d_in[12];
    const float* neg_W    = (const float*)d_in[13];
    const float* neg_Wu   = (const float*)d_in[14];
    const float* neg_Wv   = (const float*)d_in[15];
    const float* neg_b    = (const float*)d_in[16];
    const float* neg_projW= (const float*)d_in[17];
    const float* neg_projb= (const float*)d_in[18];
    const float* self_W   = (const float*)d_in[19];
    const float* self_b   = (const float*)d_in[20];
    const float* mlpp_W   = (const float*)d_in[21];
    const float* mlpp_b   = (const float*)d_in[22];
    const float* mlpn_W   = (const float*)d_in[23];
    const float* mlpn_b   = (const float*)d_in[24];
    const float* sem_W1   = (const float*)d_in[25];
    const float* sem_b1   = (const float*)d_in[26];
    const float* sem_W2   = (const float*)d_in[27];
    const float* pred_W   = (const float*)d_in[28];
    const float* pred_b   = (const float*)d_in[29];

    prep_kernel<<<48, 256>>>(Whh);
    gru_kernel<<<NN / 4, 64>>>(inputs, Wih, bih, bhh,
                               pos_W, neg_W, pos_Wu, pos_Wv, neg_Wu, neg_Wv);
    attn_kernel<<<dim3(NN, 2), 256>>>(pos_adj, neg_adj);
    comb_kernel<<<(NN + 15) / 16, 256>>>(pos_b, pos_projW, pos_projb, neg_b, neg_projW, neg_projb,
                                         self_W, self_b, mlpp_W, mlpp_b, mlpn_W, mlpn_b,
                                         sem_W1, sem_b1, sem_W2);
    final_kernel<<<NN / 4, 128>>>(pred_W, pred_b, (float*)d_out);
}